// round 8
// baseline (speedup 1.0000x reference)
#include <cuda_runtime.h>
#include <math.h>
#include <float.h>

#define BB 32
#define HH 56
#define WW 56
#define CC 256
#define HW (HH*WW)
#define NB (BB*14)   // 448 blocks per streaming pass (4 rows x 64 c-quads each)

// ---------------- scratch (device globals) ---------------------------------------
__device__ __align__(16) float g_pool1[BB*HH*CC*2];   // [b][h][c][{max,mean}]
__device__ __align__(16) float g_pool2[BB*CC*WW*2];   // [b][c][w][{max,mean}]
__device__ __align__(16) float g_pool3[BB*HH*WW*2];   // [b][h][w][{max,mean}]
__device__ __align__(16) float g_a1 [BB*HH*CC];       // [b][h][c]
__device__ __align__(16) float g_a2t[BB*WW*CC];       // [b][w][c]
__device__ __align__(16) float g_a3 [BB*HH*WW];       // [b][h][w]
__device__ __align__(16) float g_gap[BB*CC];          // atomically-reduced x*a3 sums
__device__ __align__(16) float g_cw[BB*CC];           // SE channel gate
__device__ unsigned int g_ticket[BB];                 // monotonic arrival tickets
__device__ unsigned int g_flag[BB];                   // monotonic per-batch done flag

__device__ __forceinline__ float4 f4max(float4 a, float4 b) {
    return make_float4(fmaxf(a.x,b.x), fmaxf(a.y,b.y), fmaxf(a.z,b.z), fmaxf(a.w,b.w));
}

// ---------------- all three pools, one kernel (also zeroes g_gap) -----------------
__global__ __launch_bounds__(256) void pools_kernel(const float* __restrict__ x) {
    int t = threadIdx.x;
    int sub = t >> 6;          // 0..3
    int c4  = t & 63;          // c-quad index

    if (blockIdx.x < 32) g_gap[blockIdx.x*CC + t] = 0.f;   // zero for gsf atomics

    if (blockIdx.x < NB) {
        int b = blockIdx.x / 14, hq = blockIdx.x % 14;
        int h = hq*4 + sub;
        int bh = b*HH + h;
        const float* xp = x + (size_t)bh*(WW*CC) + c4*4;

        int lane = t & 31;
        int half = c4 >> 5;
        __shared__ float2 s3[4][WW][16];    // 16 partials per (h_local, w)

        float4 mx = make_float4(-FLT_MAX,-FLT_MAX,-FLT_MAX,-FLT_MAX);
        float4 sm = make_float4(0.f,0.f,0.f,0.f);
        #pragma unroll 8
        for (int w = 0; w < WW; ++w) {
            float4 v = *(const float4*)(xp + w*CC);
            mx = f4max(mx, v);
            sm.x += v.x; sm.y += v.y; sm.z += v.z; sm.w += v.w;
            // pool3 partial: 2-step butterfly -> 8 lane-groups
            float m = fmaxf(fmaxf(v.x,v.y), fmaxf(v.z,v.w));
            float s = v.x+v.y+v.z+v.w;
            m = fmaxf(m, __shfl_xor_sync(0xFFFFFFFFu, m, 16));
            s += __shfl_xor_sync(0xFFFFFFFFu, s, 16);
            m = fmaxf(m, __shfl_xor_sync(0xFFFFFFFFu, m, 8));
            s += __shfl_xor_sync(0xFFFFFFFFu, s, 8);
            if (lane < 8) s3[sub][w][half*8 + lane] = make_float2(m, s);
        }
        {
            const float invw = 1.f/WW;
            float4* o = (float4*)(g_pool1 + ((size_t)bh*CC + c4*4)*2);
            o[0] = make_float4(mx.x, sm.x*invw, mx.y, sm.y*invw);
            o[1] = make_float4(mx.z, sm.z*invw, mx.w, sm.w*invw);
        }
        __syncthreads();
        if (t < 224) {
            int hl = t / WW, w = t % WW;
            float2 p = s3[hl][w][0];
            float m = p.x, s = p.y;
            #pragma unroll
            for (int k = 1; k < 16; ++k) {
                float2 q = s3[hl][w][k];
                m = fmaxf(m, q.x); s += q.y;
            }
            int o = ((b*HH + hq*4 + hl)*WW + w)*2;
            g_pool3[o]   = m;
            g_pool3[o+1] = s * (1.f/CC);
        }
    } else {
        int blk = blockIdx.x - NB;
        int b = blk / 14, wq = blk % 14;
        int w = wq*4 + sub;
        const float* xp = x + ((size_t)b*HW + w)*CC + c4*4;
        float4 mx = make_float4(-FLT_MAX,-FLT_MAX,-FLT_MAX,-FLT_MAX);
        float4 sm = make_float4(0.f,0.f,0.f,0.f);
        #pragma unroll 8
        for (int h = 0; h < HH; ++h) {
            float4 v = *(const float4*)(xp + (size_t)h*WW*CC);
            mx = f4max(mx, v);
            sm.x += v.x; sm.y += v.y; sm.z += v.z; sm.w += v.w;
        }
        const float invh = 1.f/HH;
        float2* o = (float2*)g_pool2 + ((size_t)b*CC + c4*4)*WW + w;
        o[0]    = make_float2(mx.x, sm.x*invh);
        o[WW]   = make_float2(mx.y, sm.y*invh);
        o[2*WW] = make_float2(mx.z, sm.z*invh);
        o[3*WW] = make_float2(mx.w, sm.w*invh);
    }
}

// ---------------- 7x7 conv (2ch->1) + BN + sigmoid, smem-tiled, branchless -------
template<int HC, int WC, int MODE>
__device__ __forceinline__ void do_conv(
    float2* tile, float2* wsm,
    const float* __restrict__ in, float* __restrict__ out,
    int b, int t0, float sc, float sh, float bs)
{
    const int TI = 8;
    const int PW = WC + 6;
    int tid = threadIdx.x;
    int i0 = t0 * TI;

    const float2* inb = (const float2*)in + (size_t)b*HC*WC;
    for (int idx = tid; idx < (TI+6)*PW; idx += 256) {
        int r = idx / PW, col = idx - r*PW;
        int i2 = i0 + r - 3, j2 = col - 3;
        float2 v = make_float2(0.f, 0.f);
        if (i2 >= 0 && i2 < HC && j2 >= 0 && j2 < WC)
            v = inb[i2*WC + j2];
        tile[idx] = v;
    }
    __syncthreads();

    for (int o = tid; o < TI*WC; o += 256) {
        int r = o / WC, j = o - r*WC;
        const float2* base = tile + r*PW + j;
        float acc = bs;
        #pragma unroll
        for (int kh = 0; kh < 7; ++kh) {
            #pragma unroll
            for (int kw = 0; kw < 7; ++kw) {
                float2 v = base[kh*PW + kw];
                float2 w = wsm[kh*7 + kw];
                acc = fmaf(v.x, w.x, acc);
                acc = fmaf(v.y, w.y, acc);
            }
        }
        float y = acc*sc + sh;
        float a = 1.f / (1.f + __expf(-y));
        int i = i0 + r;
        size_t oo = MODE ? ((size_t)b*WC + j)*HC + i
                         : ((size_t)b*HC + i)*WC + j;
        out[oo] = a;
    }
}

__global__ void conv_all_kernel(
    const float* __restrict__ c1w, const float* __restrict__ c1b,
    const float* __restrict__ b1g, const float* __restrict__ b1b,
    const float* __restrict__ b1m, const float* __restrict__ b1v,
    const float* __restrict__ c2w, const float* __restrict__ c2b,
    const float* __restrict__ b2g, const float* __restrict__ b2b,
    const float* __restrict__ b2m, const float* __restrict__ b2v,
    const float* __restrict__ c3w, const float* __restrict__ c3b,
    const float* __restrict__ b3g, const float* __restrict__ b3b,
    const float* __restrict__ b3m, const float* __restrict__ b3v)
{
    __shared__ float2 tile[14*262];
    __shared__ float2 wsm[49];

    int bx = blockIdx.x;
    int which, b, t0;
    const float *wc, *bc, *bg, *bb, *bm, *bv;
    if (bx < 224)        { which = 0; int r = bx;        b = r/7;  t0 = r%7;
                           wc=c1w; bc=c1b; bg=b1g; bb=b1b; bm=b1m; bv=b1v; }
    else if (bx < 1248)  { which = 1; int r = bx - 224;  b = r/32; t0 = r%32;
                           wc=c2w; bc=c2b; bg=b2g; bb=b2b; bm=b2m; bv=b2v; }
    else                 { which = 2; int r = bx - 1248; b = r/7;  t0 = r%7;
                           wc=c3w; bc=c3b; bg=b3g; bb=b3b; bm=b3m; bv=b3v; }

    if (threadIdx.x < 49) wsm[threadIdx.x] = ((const float2*)wc)[threadIdx.x];
    float sc = bg[0] * rsqrtf(bv[0] + 1e-3f);
    float sh = bb[0] - bm[0]*sc;
    float bs = bc[0];
    __syncthreads();

    if (which == 0)
        do_conv<HH, CC, 0>(tile, wsm, g_pool1, g_a1,  b, t0, sc, sh, bs);
    else if (which == 1)
        do_conv<CC, WW, 1>(tile, wsm, g_pool2, g_a2t, b, t0, sc, sh, bs);
    else
        do_conv<HH, WW, 0>(tile, wsm, g_pool3, g_a3,  b, t0, sc, sh, bs);
}

// ---------------- fused gap + SE + final ------------------------------------------
// gap phase only accumulates x*a3; the x*a1 and x*a2 gap terms are computed
// analytically from the pool means inside the SE (last) block.
__global__ __launch_bounds__(256, 4) void gsf_kernel(
        const float* __restrict__ x, float* __restrict__ out,
        const float* __restrict__ w1, const float* __restrict__ b1,
        const float* __restrict__ w2, const float* __restrict__ b2) {
    int t = threadIdx.x;
    int sub = t >> 6, c4 = t & 63;
    int b = blockIdx.x / 14, hq = blockIdx.x % 14;
    int h = hq*4 + sub;
    int bh = b*HH + h;

    __shared__ unsigned int s_f0;
    __shared__ int s_last;
    if (t == 0) s_f0 = atomicAdd(&g_flag[b], 0u);   // snapshot BEFORE ticketing

    size_t base = (size_t)bh*(WW*CC) + c4*4;
    const float* a3p = g_a3 + bh*WW;

    // ---- gap phase: only x*a3 ----
    float4 acc = make_float4(0.f,0.f,0.f,0.f);
    #pragma unroll 8
    for (int w = 0; w < WW; ++w) {
        float4 xv = *(const float4*)(x + base + w*CC);
        float a3 = a3p[w];
        acc.x = fmaf(xv.x, a3, acc.x);
        acc.y = fmaf(xv.y, a3, acc.y);
        acc.z = fmaf(xv.z, a3, acc.z);
        acc.w = fmaf(xv.w, a3, acc.w);
    }
    __shared__ float4 sa[4][64];
    sa[sub][c4] = acc;
    __syncthreads();
    if (t < 64) {
        float4 s = sa[0][t];
        #pragma unroll
        for (int g = 1; g < 4; ++g) {
            float4 q = sa[g][t];
            s.x += q.x; s.y += q.y; s.z += q.z; s.w += q.w;
        }
        float* gp = g_gap + b*CC + t*4;
        atomicAdd(gp+0, s.x);
        atomicAdd(gp+1, s.y);
        atomicAdd(gp+2, s.z);
        atomicAdd(gp+3, s.w);
    }
    __threadfence();                                 // release our partial sums
    if (t == 0) {
        unsigned int old = atomicAdd(&g_ticket[b], 1u);
        s_last = ((old % 14u) == 13u);
    }
    __syncthreads();

    if (s_last) {
        __threadfence();                             // acquire
        __shared__ float g[CC];
        __shared__ float hbuf[32];

        // analytic gap terms from pool means: c = t
        float gap12 = 0.f;
        {
            const float* a1p = g_a1 + (size_t)b*HH*CC + t;
            const float* p1p = g_pool1 + ((size_t)b*HH*CC + t)*2 + 1;
            #pragma unroll 8
            for (int hh = 0; hh < HH; ++hh)
                gap12 = fmaf(a1p[hh*CC], p1p[hh*CC*2], gap12);
            const float* a2pp = g_a2t + (size_t)b*WW*CC + t;
            const float2* p2p = (const float2*)g_pool2 + ((size_t)b*CC + t)*WW;
            #pragma unroll 8
            for (int w = 0; w < WW; ++w)
                gap12 = fmaf(a2pp[w*CC], p2p[w].y, gap12);
        }
        g[t] = (g_gap[b*CC + t] + gap12 * (float)WW) * (1.f/(HH*WW));
        __syncthreads();

        int d = t >> 3, grp = t & 7;
        float a = 0.f;
        #pragma unroll
        for (int k = 0; k < 32; ++k) {
            int c = grp + 8*k;
            a = fmaf(g[c], __ldg(w1 + c*32 + d), a);
        }
        a += __shfl_xor_sync(0xFFFFFFFFu, a, 1);
        a += __shfl_xor_sync(0xFFFFFFFFu, a, 2);
        a += __shfl_xor_sync(0xFFFFFFFFu, a, 4);
        if (grp == 0) hbuf[d] = fmaxf(a + __ldg(b1 + d), 0.f);
        __syncthreads();
        float av = __ldg(b2 + t);
        #pragma unroll
        for (int dd = 0; dd < 32; ++dd)
            av = fmaf(hbuf[dd], __ldg(w2 + dd*CC + t), av);
        g_cw[b*CC + t] = 1.f / (1.f + __expf(-av));
        __threadfence();                             // release cw
        __syncthreads();
        if (t == 0) atomicAdd(&g_flag[b], 1u);
    } else {
        if (t == 0) {
            while (atomicAdd(&g_flag[b], 0u) == s_f0) __nanosleep(200);
        }
        __syncthreads();
        __threadfence();                             // acquire cw
    }

    // ---- final phase: out = x * (a1+a2+a3) * cw ----
    const float* a2p = g_a2t + (size_t)b*WW*CC + c4*4;
    float4 ra1 = *((const float4*)(g_a1 + (size_t)bh*CC) + c4);
    float4 rcw = *((const float4*)(g_cw + (size_t)b*CC) + c4);
    #pragma unroll 8
    for (int w = 0; w < WW; ++w) {
        float4 xv = *(const float4*)(x + base + w*CC);
        float4 a2 = *(const float4*)(a2p + w*CC);
        float a3 = a3p[w];
        float4 o;
        o.x = xv.x * (ra1.x + a2.x + a3) * rcw.x;
        o.y = xv.y * (ra1.y + a2.y + a3) * rcw.y;
        o.z = xv.z * (ra1.z + a2.z + a3) * rcw.z;
        o.w = xv.w * (ra1.w + a2.w + a3) * rcw.w;
        *(float4*)(out + base + w*CC) = o;
    }
}

// ---------------- launch ----------------------------------------------------------
extern "C" void kernel_launch(void* const* d_in, const int* in_sizes, int n_in,
                              void* d_out, int out_size) {
    const float* x   = (const float*)d_in[0];
    const float* c1w = (const float*)d_in[1];
    const float* c1b = (const float*)d_in[2];
    const float* b1g = (const float*)d_in[3];
    const float* b1b = (const float*)d_in[4];
    const float* b1m = (const float*)d_in[5];
    const float* b1v = (const float*)d_in[6];
    const float* c2w = (const float*)d_in[7];
    const float* c2b = (const float*)d_in[8];
    const float* b2g = (const float*)d_in[9];
    const float* b2b = (const float*)d_in[10];
    const float* b2m = (const float*)d_in[11];
    const float* b2v = (const float*)d_in[12];
    const float* c3w = (const float*)d_in[13];
    const float* c3b = (const float*)d_in[14];
    const float* b3g = (const float*)d_in[15];
    const float* b3b = (const float*)d_in[16];
    const float* b3m = (const float*)d_in[17];
    const float* b3v = (const float*)d_in[18];
    const float* sw1 = (const float*)d_in[19];
    const float* sb1 = (const float*)d_in[20];
    const float* sw2 = (const float*)d_in[21];
    const float* sb2 = (const float*)d_in[22];
    float* out = (float*)d_out;

    pools_kernel<<<2*NB, 256>>>(x);
    conv_all_kernel<<<1472, 256>>>(
        c1w, c1b, b1g, b1b, b1m, b1v,
        c2w, c2b, b2g, b2b, b2m, b2v,
        c3w, c3b, b3g, b3b, b3m, b3v);
    gsf_kernel<<<NB, 256>>>(x, out, sw1, sb1, sw2, sb2);
}

// round 10
// speedup vs baseline: 1.4262x; 1.4262x over previous
#include <cuda_runtime.h>
#include <math.h>
#include <float.h>

#define BB 32
#define HH 56
#define WW 56
#define CC 256
#define HW (HH*WW)
#define NB (BB*14)   // 448 blocks per streaming pass (4 rows x 64 c-quads each)

// ---------------- scratch (device globals) ---------------------------------------
__device__ __align__(16) float g_pool1[BB*HH*CC*2];   // [b][h][c][{max,mean}]
__device__ __align__(16) float g_pool2[BB*CC*WW*2];   // [b][c][w][{max,mean}]
__device__ __align__(16) float g_pool3[BB*HH*WW*2];   // [b][h][w][{max,mean}]
__device__ __align__(16) float g_a1 [BB*HH*CC];       // [b][h][c]
__device__ __align__(16) float g_a2t[BB*WW*CC];       // [b][w][c]
__device__ __align__(16) float g_a3 [BB*HH*WW];       // [b][h][w]
__device__ __align__(16) float g_gap[BB*CC];          // atomically-reduced gap sums
__device__ __align__(16) float g_cw[BB*CC];           // SE channel gate
__device__ unsigned int g_ticket[BB];                 // monotonic arrival tickets
__device__ unsigned int g_flag[BB];                   // monotonic per-batch done flag

__device__ __forceinline__ float4 f4max(float4 a, float4 b) {
    return make_float4(fmaxf(a.x,b.x), fmaxf(a.y,b.y), fmaxf(a.z,b.z), fmaxf(a.w,b.w));
}

// ---------------- all three pools, one kernel (also zeroes g_gap) -----------------
// pool13 inner loop is software-pipelined: 4 independent loads, then 4
// interleaved shfl reduction chains (hides SHFL latency).
__global__ __launch_bounds__(256, 2) void pools_kernel(const float* __restrict__ x) {
    int t = threadIdx.x;
    int sub = t >> 6;          // 0..3
    int c4  = t & 63;          // c-quad index

    if (blockIdx.x < 32) g_gap[blockIdx.x*CC + t] = 0.f;   // zero for gsf atomics

    if (blockIdx.x < NB) {
        int b = blockIdx.x / 14, hq = blockIdx.x % 14;
        int h = hq*4 + sub;
        int bh = b*HH + h;
        const float* xp = x + (size_t)bh*(WW*CC) + c4*4;

        int lane = t & 31;
        int half = c4 >> 5;
        __shared__ float2 s3[4][WW][2];

        float4 mx = make_float4(-FLT_MAX,-FLT_MAX,-FLT_MAX,-FLT_MAX);
        float4 sm = make_float4(0.f,0.f,0.f,0.f);

        #pragma unroll
        for (int w0 = 0; w0 < WW; w0 += 4) {
            // batch 4 independent loads
            float4 v0 = *(const float4*)(xp + (w0+0)*CC);
            float4 v1 = *(const float4*)(xp + (w0+1)*CC);
            float4 v2 = *(const float4*)(xp + (w0+2)*CC);
            float4 v3 = *(const float4*)(xp + (w0+3)*CC);
            // pool1
            mx = f4max(mx, v0); mx = f4max(mx, v1);
            mx = f4max(mx, v2); mx = f4max(mx, v3);
            sm.x += v0.x+v1.x+v2.x+v3.x;
            sm.y += v0.y+v1.y+v2.y+v3.y;
            sm.z += v0.z+v1.z+v2.z+v3.z;
            sm.w += v0.w+v1.w+v2.w+v3.w;
            // pool3: 4 interleaved shfl chains
            float m0 = fmaxf(fmaxf(v0.x,v0.y), fmaxf(v0.z,v0.w));
            float m1 = fmaxf(fmaxf(v1.x,v1.y), fmaxf(v1.z,v1.w));
            float m2 = fmaxf(fmaxf(v2.x,v2.y), fmaxf(v2.z,v2.w));
            float m3 = fmaxf(fmaxf(v3.x,v3.y), fmaxf(v3.z,v3.w));
            float s0 = v0.x+v0.y+v0.z+v0.w;
            float s1 = v1.x+v1.y+v1.z+v1.w;
            float s2 = v2.x+v2.y+v2.z+v2.w;
            float s3v = v3.x+v3.y+v3.z+v3.w;
            #pragma unroll
            for (int off = 16; off; off >>= 1) {
                m0 = fmaxf(m0, __shfl_xor_sync(0xFFFFFFFFu, m0, off));
                m1 = fmaxf(m1, __shfl_xor_sync(0xFFFFFFFFu, m1, off));
                m2 = fmaxf(m2, __shfl_xor_sync(0xFFFFFFFFu, m2, off));
                m3 = fmaxf(m3, __shfl_xor_sync(0xFFFFFFFFu, m3, off));
                s0 += __shfl_xor_sync(0xFFFFFFFFu, s0, off);
                s1 += __shfl_xor_sync(0xFFFFFFFFu, s1, off);
                s2 += __shfl_xor_sync(0xFFFFFFFFu, s2, off);
                s3v += __shfl_xor_sync(0xFFFFFFFFu, s3v, off);
            }
            if (lane == 0) {
                s3[sub][w0+0][half] = make_float2(m0, s0);
                s3[sub][w0+1][half] = make_float2(m1, s1);
                s3[sub][w0+2][half] = make_float2(m2, s2);
                s3[sub][w0+3][half] = make_float2(m3, s3v);
            }
        }
        {
            const float invw = 1.f/WW;
            float4* o = (float4*)(g_pool1 + ((size_t)bh*CC + c4*4)*2);
            o[0] = make_float4(mx.x, sm.x*invw, mx.y, sm.y*invw);
            o[1] = make_float4(mx.z, sm.z*invw, mx.w, sm.w*invw);
        }
        __syncthreads();
        if (t < 224) {
            int hl = t / WW, w = t % WW;
            float2 p0 = s3[hl][w][0], p1 = s3[hl][w][1];
            int o = ((b*HH + hq*4 + hl)*WW + w)*2;
            g_pool3[o]   = fmaxf(p0.x, p1.x);
            g_pool3[o+1] = (p0.y + p1.y) * (1.f/CC);
        }
    } else {
        int blk = blockIdx.x - NB;
        int b = blk / 14, wq = blk % 14;
        int w = wq*4 + sub;
        const float* xp = x + ((size_t)b*HW + w)*CC + c4*4;
        float4 mx = make_float4(-FLT_MAX,-FLT_MAX,-FLT_MAX,-FLT_MAX);
        float4 sm = make_float4(0.f,0.f,0.f,0.f);
        #pragma unroll
        for (int h0 = 0; h0 < HH; h0 += 4) {
            float4 v0 = *(const float4*)(xp + (size_t)(h0+0)*WW*CC);
            float4 v1 = *(const float4*)(xp + (size_t)(h0+1)*WW*CC);
            float4 v2 = *(const float4*)(xp + (size_t)(h0+2)*WW*CC);
            float4 v3 = *(const float4*)(xp + (size_t)(h0+3)*WW*CC);
            mx = f4max(mx, v0); mx = f4max(mx, v1);
            mx = f4max(mx, v2); mx = f4max(mx, v3);
            sm.x += v0.x+v1.x+v2.x+v3.x;
            sm.y += v0.y+v1.y+v2.y+v3.y;
            sm.z += v0.z+v1.z+v2.z+v3.z;
            sm.w += v0.w+v1.w+v2.w+v3.w;
        }
        const float invh = 1.f/HH;
        float2* o = (float2*)g_pool2 + ((size_t)b*CC + c4*4)*WW + w;
        o[0]    = make_float2(mx.x, sm.x*invh);
        o[WW]   = make_float2(mx.y, sm.y*invh);
        o[2*WW] = make_float2(mx.z, sm.z*invh);
        o[3*WW] = make_float2(mx.w, sm.w*invh);
    }
}

// ---------------- 7x7 conv (2ch->1) + BN + sigmoid, smem-tiled, branchless -------
template<int HC, int WC, int MODE>
__device__ __forceinline__ void do_conv(
    float2* tile, float2* wsm,
    const float* __restrict__ in, float* __restrict__ out,
    int b, int t0, float sc, float sh, float bs)
{
    const int TI = 8;
    const int PW = WC + 6;
    int tid = threadIdx.x;
    int i0 = t0 * TI;

    const float2* inb = (const float2*)in + (size_t)b*HC*WC;
    for (int idx = tid; idx < (TI+6)*PW; idx += 256) {
        int r = idx / PW, col = idx - r*PW;
        int i2 = i0 + r - 3, j2 = col - 3;
        float2 v = make_float2(0.f, 0.f);
        if (i2 >= 0 && i2 < HC && j2 >= 0 && j2 < WC)
            v = inb[i2*WC + j2];
        tile[idx] = v;
    }
    __syncthreads();

    for (int o = tid; o < TI*WC; o += 256) {
        int r = o / WC, j = o - r*WC;
        const float2* base = tile + r*PW + j;
        float acc = bs;
        #pragma unroll
        for (int kh = 0; kh < 7; ++kh) {
            #pragma unroll
            for (int kw = 0; kw < 7; ++kw) {
                float2 v = base[kh*PW + kw];
                float2 w = wsm[kh*7 + kw];
                acc = fmaf(v.x, w.x, acc);
                acc = fmaf(v.y, w.y, acc);
            }
        }
        float y = acc*sc + sh;
        float a = 1.f / (1.f + __expf(-y));
        int i = i0 + r;
        size_t oo = MODE ? ((size_t)b*WC + j)*HC + i
                         : ((size_t)b*HC + i)*WC + j;
        out[oo] = a;
    }
}

__global__ void conv_all_kernel(
    const float* __restrict__ c1w, const float* __restrict__ c1b,
    const float* __restrict__ b1g, const float* __restrict__ b1b,
    const float* __restrict__ b1m, const float* __restrict__ b1v,
    const float* __restrict__ c2w, const float* __restrict__ c2b,
    const float* __restrict__ b2g, const float* __restrict__ b2b,
    const float* __restrict__ b2m, const float* __restrict__ b2v,
    const float* __restrict__ c3w, const float* __restrict__ c3b,
    const float* __restrict__ b3g, const float* __restrict__ b3b,
    const float* __restrict__ b3m, const float* __restrict__ b3v)
{
    __shared__ float2 tile[14*262];
    __shared__ float2 wsm[49];

    int bx = blockIdx.x;
    int which, b, t0;
    const float *wc, *bc, *bg, *bb, *bm, *bv;
    if (bx < 224)        { which = 0; int r = bx;        b = r/7;  t0 = r%7;
                           wc=c1w; bc=c1b; bg=b1g; bb=b1b; bm=b1m; bv=b1v; }
    else if (bx < 1248)  { which = 1; int r = bx - 224;  b = r/32; t0 = r%32;
                           wc=c2w; bc=c2b; bg=b2g; bb=b2b; bm=b2m; bv=b2v; }
    else                 { which = 2; int r = bx - 1248; b = r/7;  t0 = r%7;
                           wc=c3w; bc=c3b; bg=b3g; bb=b3b; bm=b3m; bv=b3v; }

    if (threadIdx.x < 49) wsm[threadIdx.x] = ((const float2*)wc)[threadIdx.x];
    float sc = bg[0] * rsqrtf(bv[0] + 1e-3f);
    float sh = bb[0] - bm[0]*sc;
    float bs = bc[0];
    __syncthreads();

    if (which == 0)
        do_conv<HH, CC, 0>(tile, wsm, g_pool1, g_a1,  b, t0, sc, sh, bs);
    else if (which == 1)
        do_conv<CC, WW, 1>(tile, wsm, g_pool2, g_a2t, b, t0, sc, sh, bs);
    else
        do_conv<HH, WW, 0>(tile, wsm, g_pool3, g_a3,  b, t0, sc, sh, bs);
}

// ---------------- fused gap + SE + final (R7 version, known good) -----------------
__global__ __launch_bounds__(256, 4) void gsf_kernel(
        const float* __restrict__ x, float* __restrict__ out,
        const float* __restrict__ w1, const float* __restrict__ b1,
        const float* __restrict__ w2, const float* __restrict__ b2) {
    int t = threadIdx.x;
    int sub = t >> 6, c4 = t & 63;
    int b = blockIdx.x / 14, hq = blockIdx.x % 14;
    int h = hq*4 + sub;
    int bh = b*HH + h;

    __shared__ unsigned int s_f0;
    __shared__ int s_last;
    if (t == 0) s_f0 = atomicAdd(&g_flag[b], 0u);   // snapshot BEFORE ticketing

    size_t base = (size_t)bh*(WW*CC) + c4*4;
    const float* a2p = g_a2t + (size_t)b*WW*CC + c4*4;
    const float* a3p = g_a3 + bh*WW;
    float4 ra1 = *((const float4*)(g_a1 + (size_t)bh*CC) + c4);

    // ---- gap phase ----
    float4 acc = make_float4(0.f,0.f,0.f,0.f);
    #pragma unroll 8
    for (int w = 0; w < WW; ++w) {
        float4 xv = *(const float4*)(x + base + w*CC);
        float4 a2 = *(const float4*)(a2p + w*CC);
        float a3 = a3p[w];
        acc.x = fmaf(xv.x, ra1.x + a2.x + a3, acc.x);
        acc.y = fmaf(xv.y, ra1.y + a2.y + a3, acc.y);
        acc.z = fmaf(xv.z, ra1.z + a2.z + a3, acc.z);
        acc.w = fmaf(xv.w, ra1.w + a2.w + a3, acc.w);
    }
    __shared__ float4 sa[4][64];
    sa[sub][c4] = acc;
    __syncthreads();
    if (t < 64) {
        float4 s = sa[0][t];
        #pragma unroll
        for (int g = 1; g < 4; ++g) {
            float4 q = sa[g][t];
            s.x += q.x; s.y += q.y; s.z += q.z; s.w += q.w;
        }
        float* gp = g_gap + b*CC + t*4;
        atomicAdd(gp+0, s.x);
        atomicAdd(gp+1, s.y);
        atomicAdd(gp+2, s.z);
        atomicAdd(gp+3, s.w);
    }
    __threadfence();                                 // release our partial sums
    if (t == 0) {
        unsigned int old = atomicAdd(&g_ticket[b], 1u);
        s_last = ((old % 14u) == 13u);
    }
    __syncthreads();

    if (s_last) {
        __threadfence();                             // acquire
        __shared__ float g[CC];
        __shared__ float hbuf[32];
        g[t] = g_gap[b*CC + t] * (1.f/(HH*WW));
        __syncthreads();
        int d = t >> 3, grp = t & 7;
        float a = 0.f;
        #pragma unroll
        for (int k = 0; k < 32; ++k) {
            int c = grp + 8*k;
            a = fmaf(g[c], __ldg(w1 + c*32 + d), a);
        }
        a += __shfl_xor_sync(0xFFFFFFFFu, a, 1);
        a += __shfl_xor_sync(0xFFFFFFFFu, a, 2);
        a += __shfl_xor_sync(0xFFFFFFFFu, a, 4);
        if (grp == 0) hbuf[d] = fmaxf(a + __ldg(b1 + d), 0.f);
        __syncthreads();
        float av = __ldg(b2 + t);
        #pragma unroll
        for (int dd = 0; dd < 32; ++dd)
            av = fmaf(hbuf[dd], __ldg(w2 + dd*CC + t), av);
        g_cw[b*CC + t] = 1.f / (1.f + __expf(-av));
        __threadfence();                             // release cw
        __syncthreads();
        if (t == 0) atomicAdd(&g_flag[b], 1u);
    } else {
        if (t == 0) {
            while (atomicAdd(&g_flag[b], 0u) == s_f0) __nanosleep(200);
        }
        __syncthreads();
        __threadfence();                             // acquire cw
    }

    // ---- final phase: out = x * (a1+a2+a3) * cw ----
    float4 rcw = *((const float4*)(g_cw + (size_t)b*CC) + c4);
    #pragma unroll 8
    for (int w = 0; w < WW; ++w) {
        float4 xv = *(const float4*)(x + base + w*CC);
        float4 a2 = *(const float4*)(a2p + w*CC);
        float a3 = a3p[w];
        float4 o;
        o.x = xv.x * (ra1.x + a2.x + a3) * rcw.x;
        o.y = xv.y * (ra1.y + a2.y + a3) * rcw.y;
        o.z = xv.z * (ra1.z + a2.z + a3) * rcw.z;
        o.w = xv.w * (ra1.w + a2.w + a3) * rcw.w;
        *(float4*)(out + base + w*CC) = o;
    }
}

// ---------------- launch ----------------------------------------------------------
extern "C" void kernel_launch(void* const* d_in, const int* in_sizes, int n_in,
                              void* d_out, int out_size) {
    const float* x   = (const float*)d_in[0];
    const float* c1w = (const float*)d_in[1];
    const float* c1b = (const float*)d_in[2];
    const float* b1g = (const float*)d_in[3];
    const float* b1b = (const float*)d_in[4];
    const float* b1m = (const float*)d_in[5];
    const float* b1v = (const float*)d_in[6];
    const float* c2w = (const float*)d_in[7];
    const float* c2b = (const float*)d_in[8];
    const float* b2g = (const float*)d_in[9];
    const float* b2b = (const float*)d_in[10];
    const float* b2m = (const float*)d_in[11];
    const float* b2v = (const float*)d_in[12];
    const float* c3w = (const float*)d_in[13];
    const float* c3b = (const float*)d_in[14];
    const float* b3g = (const float*)d_in[15];
    const float* b3b = (const float*)d_in[16];
    const float* b3m = (const float*)d_in[17];
    const float* b3v = (const float*)d_in[18];
    const float* sw1 = (const float*)d_in[19];
    const float* sb1 = (const float*)d_in[20];
    const float* sw2 = (const float*)d_in[21];
    const float* sb2 = (const float*)d_in[22];
    float* out = (float*)d_out;

    pools_kernel<<<2*NB, 256>>>(x);
    conv_all_kernel<<<1472, 256>>>(
        c1w, c1b, b1g, b1b, b1m, b1v,
        c2w, c2b, b2g, b2b, b2m, b2v,
        c3w, c3b, b3g, b3b, b3m, b3v);
    gsf_kernel<<<NB, 256>>>(x, out, sw1, sb1, sw2, sb2);
}

// round 11
// speedup vs baseline: 1.4627x; 1.0256x over previous
#include <cuda_runtime.h>
#include <math.h>
#include <float.h>

#define BB 32
#define HH 56
#define WW 56
#define CC 256
#define HW (HH*WW)
#define NB (BB*14)   // 448 blocks per streaming pass (4 rows x 64 c-quads each)

// ---------------- scratch (device globals) ---------------------------------------
__device__ __align__(16) float g_pool1[BB*HH*CC*2];   // [b][h][c][{max,mean}]
__device__ __align__(16) float g_pool2[BB*CC*WW*2];   // [b][c][w][{max,mean}]
__device__ __align__(16) float g_pool3[BB*HH*WW*2];   // [b][h][w][{max,mean}]
__device__ __align__(16) float g_a1 [BB*HH*CC];       // [b][h][c]
__device__ __align__(16) float g_a2t[BB*WW*CC];       // [b][w][c]
__device__ __align__(16) float g_a3 [BB*HH*WW];       // [b][h][w]
__device__ __align__(16) float g_gap[BB*CC];          // atomically-reduced gap sums
__device__ __align__(16) float g_cw[BB*CC];           // SE channel gate
__device__ unsigned int g_ticket[BB];                 // monotonic arrival tickets
__device__ unsigned int g_flag[BB];                   // monotonic per-batch done flag

__device__ __forceinline__ float4 f4max(float4 a, float4 b) {
    return make_float4(fmaxf(a.x,b.x), fmaxf(a.y,b.y), fmaxf(a.z,b.z), fmaxf(a.w,b.w));
}

// ---------------- all three pools, one kernel (also zeroes g_gap) -----------------
// Blocks are batch-grouped: block = b*28 + j; j<14 -> pool13(hq=j),
// j>=14 -> pool2(wq=j-14). Both halves of a batch co-resident => pool2's
// x reads hit L2 instead of DRAM.
__global__ __launch_bounds__(256, 2) void pools_kernel(const float* __restrict__ x) {
    int t = threadIdx.x;
    int sub = t >> 6;          // 0..3
    int c4  = t & 63;          // c-quad index

    if (blockIdx.x < 32) g_gap[blockIdx.x*CC + t] = 0.f;   // zero for gsf atomics

    int b = blockIdx.x / 28;
    int j = blockIdx.x % 28;

    if (j < 14) {
        int hq = j;
        int h = hq*4 + sub;
        int bh = b*HH + h;
        const float* xp = x + (size_t)bh*(WW*CC) + c4*4;

        int lane = t & 31;
        int half = c4 >> 5;
        __shared__ float2 s3[4][WW][2];

        float4 mx = make_float4(-FLT_MAX,-FLT_MAX,-FLT_MAX,-FLT_MAX);
        float4 sm = make_float4(0.f,0.f,0.f,0.f);

        #pragma unroll
        for (int w0 = 0; w0 < WW; w0 += 4) {
            float4 v0 = *(const float4*)(xp + (w0+0)*CC);
            float4 v1 = *(const float4*)(xp + (w0+1)*CC);
            float4 v2 = *(const float4*)(xp + (w0+2)*CC);
            float4 v3 = *(const float4*)(xp + (w0+3)*CC);
            mx = f4max(mx, v0); mx = f4max(mx, v1);
            mx = f4max(mx, v2); mx = f4max(mx, v3);
            sm.x += v0.x+v1.x+v2.x+v3.x;
            sm.y += v0.y+v1.y+v2.y+v3.y;
            sm.z += v0.z+v1.z+v2.z+v3.z;
            sm.w += v0.w+v1.w+v2.w+v3.w;
            float m0 = fmaxf(fmaxf(v0.x,v0.y), fmaxf(v0.z,v0.w));
            float m1 = fmaxf(fmaxf(v1.x,v1.y), fmaxf(v1.z,v1.w));
            float m2 = fmaxf(fmaxf(v2.x,v2.y), fmaxf(v2.z,v2.w));
            float m3 = fmaxf(fmaxf(v3.x,v3.y), fmaxf(v3.z,v3.w));
            float s0 = v0.x+v0.y+v0.z+v0.w;
            float s1 = v1.x+v1.y+v1.z+v1.w;
            float s2 = v2.x+v2.y+v2.z+v2.w;
            float s3v = v3.x+v3.y+v3.z+v3.w;
            #pragma unroll
            for (int off = 16; off; off >>= 1) {
                m0 = fmaxf(m0, __shfl_xor_sync(0xFFFFFFFFu, m0, off));
                m1 = fmaxf(m1, __shfl_xor_sync(0xFFFFFFFFu, m1, off));
                m2 = fmaxf(m2, __shfl_xor_sync(0xFFFFFFFFu, m2, off));
                m3 = fmaxf(m3, __shfl_xor_sync(0xFFFFFFFFu, m3, off));
                s0 += __shfl_xor_sync(0xFFFFFFFFu, s0, off);
                s1 += __shfl_xor_sync(0xFFFFFFFFu, s1, off);
                s2 += __shfl_xor_sync(0xFFFFFFFFu, s2, off);
                s3v += __shfl_xor_sync(0xFFFFFFFFu, s3v, off);
            }
            if (lane == 0) {
                s3[sub][w0+0][half] = make_float2(m0, s0);
                s3[sub][w0+1][half] = make_float2(m1, s1);
                s3[sub][w0+2][half] = make_float2(m2, s2);
                s3[sub][w0+3][half] = make_float2(m3, s3v);
            }
        }
        {
            const float invw = 1.f/WW;
            float4* o = (float4*)(g_pool1 + ((size_t)bh*CC + c4*4)*2);
            o[0] = make_float4(mx.x, sm.x*invw, mx.y, sm.y*invw);
            o[1] = make_float4(mx.z, sm.z*invw, mx.w, sm.w*invw);
        }
        __syncthreads();
        if (t < 224) {
            int hl = t / WW, w = t % WW;
            float2 p0 = s3[hl][w][0], p1 = s3[hl][w][1];
            int o = ((b*HH + hq*4 + hl)*WW + w)*2;
            g_pool3[o]   = fmaxf(p0.x, p1.x);
            g_pool3[o+1] = (p0.y + p1.y) * (1.f/CC);
        }
    } else {
        int wq = j - 14;
        int w = wq*4 + sub;
        const float* xp = x + ((size_t)b*HW + w)*CC + c4*4;
        float4 mx = make_float4(-FLT_MAX,-FLT_MAX,-FLT_MAX,-FLT_MAX);
        float4 sm = make_float4(0.f,0.f,0.f,0.f);
        #pragma unroll
        for (int h0 = 0; h0 < HH; h0 += 4) {
            float4 v0 = *(const float4*)(xp + (size_t)(h0+0)*WW*CC);
            float4 v1 = *(const float4*)(xp + (size_t)(h0+1)*WW*CC);
            float4 v2 = *(const float4*)(xp + (size_t)(h0+2)*WW*CC);
            float4 v3 = *(const float4*)(xp + (size_t)(h0+3)*WW*CC);
            mx = f4max(mx, v0); mx = f4max(mx, v1);
            mx = f4max(mx, v2); mx = f4max(mx, v3);
            sm.x += v0.x+v1.x+v2.x+v3.x;
            sm.y += v0.y+v1.y+v2.y+v3.y;
            sm.z += v0.z+v1.z+v2.z+v3.z;
            sm.w += v0.w+v1.w+v2.w+v3.w;
        }
        const float invh = 1.f/HH;
        float2* o = (float2*)g_pool2 + ((size_t)b*CC + c4*4)*WW + w;
        o[0]    = make_float2(mx.x, sm.x*invh);
        o[WW]   = make_float2(mx.y, sm.y*invh);
        o[2*WW] = make_float2(mx.z, sm.z*invh);
        o[3*WW] = make_float2(mx.w, sm.w*invh);
    }
}

// ---------------- 7x7 conv (2ch->1) + BN + sigmoid, smem-tiled, branchless -------
template<int HC, int WC, int MODE>
__device__ __forceinline__ void do_conv(
    float2* tile, float2* wsm,
    const float* __restrict__ in, float* __restrict__ out,
    int b, int t0, float sc, float sh, float bs)
{
    const int TI = 8;
    const int PW = WC + 6;
    int tid = threadIdx.x;
    int i0 = t0 * TI;

    const float2* inb = (const float2*)in + (size_t)b*HC*WC;
    for (int idx = tid; idx < (TI+6)*PW; idx += 256) {
        int r = idx / PW, col = idx - r*PW;
        int i2 = i0 + r - 3, j2 = col - 3;
        float2 v = make_float2(0.f, 0.f);
        if (i2 >= 0 && i2 < HC && j2 >= 0 && j2 < WC)
            v = inb[i2*WC + j2];
        tile[idx] = v;
    }
    __syncthreads();

    for (int o = tid; o < TI*WC; o += 256) {
        int r = o / WC, j = o - r*WC;
        const float2* base = tile + r*PW + j;
        float acc = bs;
        #pragma unroll
        for (int kh = 0; kh < 7; ++kh) {
            #pragma unroll
            for (int kw = 0; kw < 7; ++kw) {
                float2 v = base[kh*PW + kw];
                float2 w = wsm[kh*7 + kw];
                acc = fmaf(v.x, w.x, acc);
                acc = fmaf(v.y, w.y, acc);
            }
        }
        float y = acc*sc + sh;
        float a = 1.f / (1.f + __expf(-y));
        int i = i0 + r;
        size_t oo = MODE ? ((size_t)b*WC + j)*HC + i
                         : ((size_t)b*HC + i)*WC + j;
        out[oo] = a;
    }
}

__global__ void conv_all_kernel(
    const float* __restrict__ c1w, const float* __restrict__ c1b,
    const float* __restrict__ b1g, const float* __restrict__ b1b,
    const float* __restrict__ b1m, const float* __restrict__ b1v,
    const float* __restrict__ c2w, const float* __restrict__ c2b,
    const float* __restrict__ b2g, const float* __restrict__ b2b,
    const float* __restrict__ b2m, const float* __restrict__ b2v,
    const float* __restrict__ c3w, const float* __restrict__ c3b,
    const float* __restrict__ b3g, const float* __restrict__ b3b,
    const float* __restrict__ b3m, const float* __restrict__ b3v)
{
    __shared__ float2 tile[14*262];
    __shared__ float2 wsm[49];

    int bx = blockIdx.x;
    int which, b, t0;
    const float *wc, *bc, *bg, *bb, *bm, *bv;
    if (bx < 224)        { which = 0; int r = bx;        b = r/7;  t0 = r%7;
                           wc=c1w; bc=c1b; bg=b1g; bb=b1b; bm=b1m; bv=b1v; }
    else if (bx < 1248)  { which = 1; int r = bx - 224;  b = r/32; t0 = r%32;
                           wc=c2w; bc=c2b; bg=b2g; bb=b2b; bm=b2m; bv=b2v; }
    else                 { which = 2; int r = bx - 1248; b = r/7;  t0 = r%7;
                           wc=c3w; bc=c3b; bg=b3g; bb=b3b; bm=b3m; bv=b3v; }

    if (threadIdx.x < 49) wsm[threadIdx.x] = ((const float2*)wc)[threadIdx.x];
    float sc = bg[0] * rsqrtf(bv[0] + 1e-3f);
    float sh = bb[0] - bm[0]*sc;
    float bs = bc[0];
    __syncthreads();

    if (which == 0)
        do_conv<HH, CC, 0>(tile, wsm, g_pool1, g_a1,  b, t0, sc, sh, bs);
    else if (which == 1)
        do_conv<CC, WW, 1>(tile, wsm, g_pool2, g_a2t, b, t0, sc, sh, bs);
    else
        do_conv<HH, WW, 0>(tile, wsm, g_pool3, g_a3,  b, t0, sc, sh, bs);
}

// ---------------- fused gap + SE + final ------------------------------------------
__global__ __launch_bounds__(256, 4) void gsf_kernel(
        const float* __restrict__ x, float* __restrict__ out,
        const float* __restrict__ w1, const float* __restrict__ b1,
        const float* __restrict__ w2, const float* __restrict__ b2) {
    int t = threadIdx.x;
    int sub = t >> 6, c4 = t & 63;
    int b = blockIdx.x / 14, hq = blockIdx.x % 14;
    int h = hq*4 + sub;
    int bh = b*HH + h;

    __shared__ unsigned int s_f0;
    __shared__ int s_last;
    if (t == 0) s_f0 = atomicAdd(&g_flag[b], 0u);   // snapshot BEFORE ticketing

    size_t base = (size_t)bh*(WW*CC) + c4*4;
    const float* a2p = g_a2t + (size_t)b*WW*CC + c4*4;
    const float* a3p = g_a3 + bh*WW;
    float4 ra1 = *((const float4*)(g_a1 + (size_t)bh*CC) + c4);

    // ---- gap phase ----
    float4 acc = make_float4(0.f,0.f,0.f,0.f);
    #pragma unroll 8
    for (int w = 0; w < WW; ++w) {
        float4 xv = *(const float4*)(x + base + w*CC);
        float4 a2 = *(const float4*)(a2p + w*CC);
        float a3 = a3p[w];
        acc.x = fmaf(xv.x, ra1.x + a2.x + a3, acc.x);
        acc.y = fmaf(xv.y, ra1.y + a2.y + a3, acc.y);
        acc.z = fmaf(xv.z, ra1.z + a2.z + a3, acc.z);
        acc.w = fmaf(xv.w, ra1.w + a2.w + a3, acc.w);
    }
    __shared__ float4 sa[4][64];
    sa[sub][c4] = acc;
    __syncthreads();
    if (t < 64) {
        float4 s = sa[0][t];
        #pragma unroll
        for (int g = 1; g < 4; ++g) {
            float4 q = sa[g][t];
            s.x += q.x; s.y += q.y; s.z += q.z; s.w += q.w;
        }
        float* gp = g_gap + b*CC + t*4;
        atomicAdd(gp+0, s.x);
        atomicAdd(gp+1, s.y);
        atomicAdd(gp+2, s.z);
        atomicAdd(gp+3, s.w);
    }
    __threadfence();                                 // release our partial sums
    if (t == 0) {
        unsigned int old = atomicAdd(&g_ticket[b], 1u);
        s_last = ((old % 14u) == 13u);
    }
    __syncthreads();

    if (s_last) {
        __threadfence();                             // acquire
        __shared__ float g[CC];
        __shared__ float hbuf[32];
        g[t] = g_gap[b*CC + t] * (1.f/(HH*WW));
        __syncthreads();
        int d = t >> 3, grp = t & 7;
        float a = 0.f;
        #pragma unroll
        for (int k = 0; k < 32; ++k) {
            int c = grp + 8*k;
            a = fmaf(g[c], __ldg(w1 + c*32 + d), a);
        }
        a += __shfl_xor_sync(0xFFFFFFFFu, a, 1);
        a += __shfl_xor_sync(0xFFFFFFFFu, a, 2);
        a += __shfl_xor_sync(0xFFFFFFFFu, a, 4);
        if (grp == 0) hbuf[d] = fmaxf(a + __ldg(b1 + d), 0.f);
        __syncthreads();
        float av = __ldg(b2 + t);
        #pragma unroll
        for (int dd = 0; dd < 32; ++dd)
            av = fmaf(hbuf[dd], __ldg(w2 + dd*CC + t), av);
        g_cw[b*CC + t] = 1.f / (1.f + __expf(-av));
        __threadfence();                             // release cw
        __syncthreads();
        if (t == 0) atomicAdd(&g_flag[b], 1u);
    } else {
        if (t == 0) {
            while (atomicAdd(&g_flag[b], 0u) == s_f0) __nanosleep(200);
        }
        __syncthreads();
        __threadfence();                             // acquire cw
    }

    // ---- final phase: out = x * (a1+a2+a3) * cw ----
    float4 rcw = *((const float4*)(g_cw + (size_t)b*CC) + c4);
    #pragma unroll 8
    for (int w = 0; w < WW; ++w) {
        float4 xv = *(const float4*)(x + base + w*CC);
        float4 a2 = *(const float4*)(a2p + w*CC);
        float a3 = a3p[w];
        float4 o;
        o.x = xv.x * (ra1.x + a2.x + a3) * rcw.x;
        o.y = xv.y * (ra1.y + a2.y + a3) * rcw.y;
        o.z = xv.z * (ra1.z + a2.z + a3) * rcw.z;
        o.w = xv.w * (ra1.w + a2.w + a3) * rcw.w;
        *(float4*)(out + base + w*CC) = o;
    }
}

// ---------------- launch ----------------------------------------------------------
extern "C" void kernel_launch(void* const* d_in, const int* in_sizes, int n_in,
                              void* d_out, int out_size) {
    const float* x   = (const float*)d_in[0];
    const float* c1w = (const float*)d_in[1];
    const float* c1b = (const float*)d_in[2];
    const float* b1g = (const float*)d_in[3];
    const float* b1b = (const float*)d_in[4];
    const float* b1m = (const float*)d_in[5];
    const float* b1v = (const float*)d_in[6];
    const float* c2w = (const float*)d_in[7];
    const float* c2b = (const float*)d_in[8];
    const float* b2g = (const float*)d_in[9];
    const float* b2b = (const float*)d_in[10];
    const float* b2m = (const float*)d_in[11];
    const float* b2v = (const float*)d_in[12];
    const float* c3w = (const float*)d_in[13];
    const float* c3b = (const float*)d_in[14];
    const float* b3g = (const float*)d_in[15];
    const float* b3b = (const float*)d_in[16];
    const float* b3m = (const float*)d_in[17];
    const float* b3v = (const float*)d_in[18];
    const float* sw1 = (const float*)d_in[19];
    const float* sb1 = (const float*)d_in[20];
    const float* sw2 = (const float*)d_in[21];
    const float* sb2 = (const float*)d_in[22];
    float* out = (float*)d_out;

    pools_kernel<<<2*NB, 256>>>(x);
    conv_all_kernel<<<1472, 256>>>(
        c1w, c1b, b1g, b1b, b1m, b1v,
        c2w, c2b, b2g, b2b, b2m, b2v,
        c3w, c3b, b3g, b3b, b3m, b3v);
    gsf_kernel<<<NB, 256>>>(x, out, sw1, sb1, sw2, sb2);
}

// round 15
// speedup vs baseline: 1.4810x; 1.0125x over previous
#include <cuda_runtime.h>
#include <math.h>
#include <float.h>

#define BB 32
#define HH 56
#define WW 56
#define CC 256
#define HW (HH*WW)
#define NB (BB*14)   // 448 blocks per streaming pass (4 rows x 64 c-quads each)

// ---------------- scratch (device globals) ---------------------------------------
__device__ __align__(16) float g_pool1[BB*HH*CC*2];   // [b][h][c][{max,mean}]
__device__ __align__(16) float g_pool2[BB*CC*WW*2];   // [b][c][w][{max,mean}]
__device__ __align__(16) float g_pool3[BB*HH*WW*2];   // [b][h][w][{max,mean}]
__device__ __align__(16) float g_a1 [BB*HH*CC];       // [b][h][c]
__device__ __align__(16) float g_a2t[BB*WW*CC];       // [b][w][c]
__device__ __align__(16) float g_a3 [BB*HH*WW];       // [b][h][w]
__device__ __align__(16) float g_gap[BB*CC];          // atomically-reduced gap sums
__device__ __align__(16) float g_cw[BB*CC];           // SE channel gate
__device__ unsigned int g_ticket[BB];                 // monotonic arrival tickets
__device__ unsigned int g_flag[BB];                   // monotonic per-batch done flag

__device__ __forceinline__ float4 f4max(float4 a, float4 b) {
    return make_float4(fmaxf(a.x,b.x), fmaxf(a.y,b.y), fmaxf(a.z,b.z), fmaxf(a.w,b.w));
}

// ---------------- all three pools, one kernel (also zeroes g_gap) -----------------
// Batch-grouped blocks (pool13/pool2 of one batch co-resident -> L2 reuse).
// Inner loops batch 8 independent float4 loads for MLP=8.
__global__ __launch_bounds__(256, 2) void pools_kernel(const float* __restrict__ x) {
    int t = threadIdx.x;
    int sub = t >> 6;          // 0..3
    int c4  = t & 63;          // c-quad index

    if (blockIdx.x < 32) g_gap[blockIdx.x*CC + t] = 0.f;   // zero for gsf atomics

    int b = blockIdx.x / 28;
    int j = blockIdx.x % 28;

    if (j < 14) {
        int hq = j;
        int h = hq*4 + sub;
        int bh = b*HH + h;
        const float* xp = x + (size_t)bh*(WW*CC) + c4*4;

        int lane = t & 31;
        int half = c4 >> 5;
        __shared__ float2 s3[4][WW][2];

        float4 mx = make_float4(-FLT_MAX,-FLT_MAX,-FLT_MAX,-FLT_MAX);
        float4 sm = make_float4(0.f,0.f,0.f,0.f);

        #pragma unroll
        for (int w0 = 0; w0 < WW; w0 += 8) {
            // batch 8 independent loads
            float4 v0 = *(const float4*)(xp + (w0+0)*CC);
            float4 v1 = *(const float4*)(xp + (w0+1)*CC);
            float4 v2 = *(const float4*)(xp + (w0+2)*CC);
            float4 v3 = *(const float4*)(xp + (w0+3)*CC);
            float4 v4 = *(const float4*)(xp + (w0+4)*CC);
            float4 v5 = *(const float4*)(xp + (w0+5)*CC);
            float4 v6 = *(const float4*)(xp + (w0+6)*CC);
            float4 v7 = *(const float4*)(xp + (w0+7)*CC);
            // pool1
            mx = f4max(mx, v0); mx = f4max(mx, v1);
            mx = f4max(mx, v2); mx = f4max(mx, v3);
            mx = f4max(mx, v4); mx = f4max(mx, v5);
            mx = f4max(mx, v6); mx = f4max(mx, v7);
            sm.x += (v0.x+v1.x+v2.x+v3.x) + (v4.x+v5.x+v6.x+v7.x);
            sm.y += (v0.y+v1.y+v2.y+v3.y) + (v4.y+v5.y+v6.y+v7.y);
            sm.z += (v0.z+v1.z+v2.z+v3.z) + (v4.z+v5.z+v6.z+v7.z);
            sm.w += (v0.w+v1.w+v2.w+v3.w) + (v4.w+v5.w+v6.w+v7.w);
            // pool3: 8 interleaved shfl chains
            float m0 = fmaxf(fmaxf(v0.x,v0.y), fmaxf(v0.z,v0.w));
            float m1 = fmaxf(fmaxf(v1.x,v1.y), fmaxf(v1.z,v1.w));
            float m2 = fmaxf(fmaxf(v2.x,v2.y), fmaxf(v2.z,v2.w));
            float m3 = fmaxf(fmaxf(v3.x,v3.y), fmaxf(v3.z,v3.w));
            float m4 = fmaxf(fmaxf(v4.x,v4.y), fmaxf(v4.z,v4.w));
            float m5 = fmaxf(fmaxf(v5.x,v5.y), fmaxf(v5.z,v5.w));
            float m6 = fmaxf(fmaxf(v6.x,v6.y), fmaxf(v6.z,v6.w));
            float m7 = fmaxf(fmaxf(v7.x,v7.y), fmaxf(v7.z,v7.w));
            float s0 = v0.x+v0.y+v0.z+v0.w;
            float s1 = v1.x+v1.y+v1.z+v1.w;
            float s2 = v2.x+v2.y+v2.z+v2.w;
            float s3v = v3.x+v3.y+v3.z+v3.w;
            float s4 = v4.x+v4.y+v4.z+v4.w;
            float s5 = v5.x+v5.y+v5.z+v5.w;
            float s6 = v6.x+v6.y+v6.z+v6.w;
            float s7 = v7.x+v7.y+v7.z+v7.w;
            #pragma unroll
            for (int off = 16; off; off >>= 1) {
                m0 = fmaxf(m0, __shfl_xor_sync(0xFFFFFFFFu, m0, off));
                m1 = fmaxf(m1, __shfl_xor_sync(0xFFFFFFFFu, m1, off));
                m2 = fmaxf(m2, __shfl_xor_sync(0xFFFFFFFFu, m2, off));
                m3 = fmaxf(m3, __shfl_xor_sync(0xFFFFFFFFu, m3, off));
                m4 = fmaxf(m4, __shfl_xor_sync(0xFFFFFFFFu, m4, off));
                m5 = fmaxf(m5, __shfl_xor_sync(0xFFFFFFFFu, m5, off));
                m6 = fmaxf(m6, __shfl_xor_sync(0xFFFFFFFFu, m6, off));
                m7 = fmaxf(m7, __shfl_xor_sync(0xFFFFFFFFu, m7, off));
                s0 += __shfl_xor_sync(0xFFFFFFFFu, s0, off);
                s1 += __shfl_xor_sync(0xFFFFFFFFu, s1, off);
                s2 += __shfl_xor_sync(0xFFFFFFFFu, s2, off);
                s3v += __shfl_xor_sync(0xFFFFFFFFu, s3v, off);
                s4 += __shfl_xor_sync(0xFFFFFFFFu, s4, off);
                s5 += __shfl_xor_sync(0xFFFFFFFFu, s5, off);
                s6 += __shfl_xor_sync(0xFFFFFFFFu, s6, off);
                s7 += __shfl_xor_sync(0xFFFFFFFFu, s7, off);
            }
            if (lane == 0) {
                s3[sub][w0+0][half] = make_float2(m0, s0);
                s3[sub][w0+1][half] = make_float2(m1, s1);
                s3[sub][w0+2][half] = make_float2(m2, s2);
                s3[sub][w0+3][half] = make_float2(m3, s3v);
                s3[sub][w0+4][half] = make_float2(m4, s4);
                s3[sub][w0+5][half] = make_float2(m5, s5);
                s3[sub][w0+6][half] = make_float2(m6, s6);
                s3[sub][w0+7][half] = make_float2(m7, s7);
            }
        }
        {
            const float invw = 1.f/WW;
            float4* o = (float4*)(g_pool1 + ((size_t)bh*CC + c4*4)*2);
            o[0] = make_float4(mx.x, sm.x*invw, mx.y, sm.y*invw);
            o[1] = make_float4(mx.z, sm.z*invw, mx.w, sm.w*invw);
        }
        __syncthreads();
        if (t < 224) {
            int hl = t / WW, w = t % WW;
            float2 p0 = s3[hl][w][0], p1 = s3[hl][w][1];
            int o = ((b*HH + hq*4 + hl)*WW + w)*2;
            g_pool3[o]   = fmaxf(p0.x, p1.x);
            g_pool3[o+1] = (p0.y + p1.y) * (1.f/CC);
        }
    } else {
        int wq = j - 14;
        int w = wq*4 + sub;
        const float* xp = x + ((size_t)b*HW + w)*CC + c4*4;
        float4 mx = make_float4(-FLT_MAX,-FLT_MAX,-FLT_MAX,-FLT_MAX);
        float4 sm = make_float4(0.f,0.f,0.f,0.f);
        #pragma unroll
        for (int h0 = 0; h0 < HH; h0 += 8) {
            float4 v0 = *(const float4*)(xp + (size_t)(h0+0)*WW*CC);
            float4 v1 = *(const float4*)(xp + (size_t)(h0+1)*WW*CC);
            float4 v2 = *(const float4*)(xp + (size_t)(h0+2)*WW*CC);
            float4 v3 = *(const float4*)(xp + (size_t)(h0+3)*WW*CC);
            float4 v4 = *(const float4*)(xp + (size_t)(h0+4)*WW*CC);
            float4 v5 = *(const float4*)(xp + (size_t)(h0+5)*WW*CC);
            float4 v6 = *(const float4*)(xp + (size_t)(h0+6)*WW*CC);
            float4 v7 = *(const float4*)(xp + (size_t)(h0+7)*WW*CC);
            mx = f4max(mx, v0); mx = f4max(mx, v1);
            mx = f4max(mx, v2); mx = f4max(mx, v3);
            mx = f4max(mx, v4); mx = f4max(mx, v5);
            mx = f4max(mx, v6); mx = f4max(mx, v7);
            sm.x += (v0.x+v1.x+v2.x+v3.x) + (v4.x+v5.x+v6.x+v7.x);
            sm.y += (v0.y+v1.y+v2.y+v3.y) + (v4.y+v5.y+v6.y+v7.y);
            sm.z += (v0.z+v1.z+v2.z+v3.z) + (v4.z+v5.z+v6.z+v7.z);
            sm.w += (v0.w+v1.w+v2.w+v3.w) + (v4.w+v5.w+v6.w+v7.w);
        }
        const float invh = 1.f/HH;
        float2* o = (float2*)g_pool2 + ((size_t)b*CC + c4*4)*WW + w;
        o[0]    = make_float2(mx.x, sm.x*invh);
        o[WW]   = make_float2(mx.y, sm.y*invh);
        o[2*WW] = make_float2(mx.z, sm.z*invh);
        o[3*WW] = make_float2(mx.w, sm.w*invh);
    }
}

// ---------------- 7x7 conv (2ch->1) + BN + sigmoid, smem-tiled, branchless -------
template<int HC, int WC, int MODE>
__device__ __forceinline__ void do_conv(
    float2* tile, float2* wsm,
    const float* __restrict__ in, float* __restrict__ out,
    int b, int t0, float sc, float sh, float bs)
{
    const int TI = 8;
    const int PW = WC + 6;
    int tid = threadIdx.x;
    int i0 = t0 * TI;

    const float2* inb = (const float2*)in + (size_t)b*HC*WC;
    for (int idx = tid; idx < (TI+6)*PW; idx += 256) {
        int r = idx / PW, col = idx - r*PW;
        int i2 = i0 + r - 3, j2 = col - 3;
        float2 v = make_float2(0.f, 0.f);
        if (i2 >= 0 && i2 < HC && j2 >= 0 && j2 < WC)
            v = inb[i2*WC + j2];
        tile[idx] = v;
    }
    __syncthreads();

    for (int o = tid; o < TI*WC; o += 256) {
        int r = o / WC, j = o - r*WC;
        const float2* base = tile + r*PW + j;
        float acc = bs;
        #pragma unroll
        for (int kh = 0; kh < 7; ++kh) {
            #pragma unroll
            for (int kw = 0; kw < 7; ++kw) {
                float2 v = base[kh*PW + kw];
                float2 w = wsm[kh*7 + kw];
                acc = fmaf(v.x, w.x, acc);
                acc = fmaf(v.y, w.y, acc);
            }
        }
        float y = acc*sc + sh;
        float a = 1.f / (1.f + __expf(-y));
        int i = i0 + r;
        size_t oo = MODE ? ((size_t)b*WC + j)*HC + i
                         : ((size_t)b*HC + i)*WC + j;
        out[oo] = a;
    }
}

__global__ void conv_all_kernel(
    const float* __restrict__ c1w, const float* __restrict__ c1b,
    const float* __restrict__ b1g, const float* __restrict__ b1b,
    const float* __restrict__ b1m, const float* __restrict__ b1v,
    const float* __restrict__ c2w, const float* __restrict__ c2b,
    const float* __restrict__ b2g, const float* __restrict__ b2b,
    const float* __restrict__ b2m, const float* __restrict__ b2v,
    const float* __restrict__ c3w, const float* __restrict__ c3b,
    const float* __restrict__ b3g, const float* __restrict__ b3b,
    const float* __restrict__ b3m, const float* __restrict__ b3v)
{
    __shared__ float2 tile[14*262];
    __shared__ float2 wsm[49];

    int bx = blockIdx.x;
    int which, b, t0;
    const float *wc, *bc, *bg, *bb, *bm, *bv;
    if (bx < 224)        { which = 0; int r = bx;        b = r/7;  t0 = r%7;
                           wc=c1w; bc=c1b; bg=b1g; bb=b1b; bm=b1m; bv=b1v; }
    else if (bx < 1248)  { which = 1; int r = bx - 224;  b = r/32; t0 = r%32;
                           wc=c2w; bc=c2b; bg=b2g; bb=b2b; bm=b2m; bv=b2v; }
    else                 { which = 2; int r = bx - 1248; b = r/7;  t0 = r%7;
                           wc=c3w; bc=c3b; bg=b3g; bb=b3b; bm=b3m; bv=b3v; }

    if (threadIdx.x < 49) wsm[threadIdx.x] = ((const float2*)wc)[threadIdx.x];
    float sc = bg[0] * rsqrtf(bv[0] + 1e-3f);
    float sh = bb[0] - bm[0]*sc;
    float bs = bc[0];
    __syncthreads();

    if (which == 0)
        do_conv<HH, CC, 0>(tile, wsm, g_pool1, g_a1,  b, t0, sc, sh, bs);
    else if (which == 1)
        do_conv<CC, WW, 1>(tile, wsm, g_pool2, g_a2t, b, t0, sc, sh, bs);
    else
        do_conv<HH, WW, 0>(tile, wsm, g_pool3, g_a3,  b, t0, sc, sh, bs);
}

// ---------------- fused gap + SE + final ------------------------------------------
__global__ __launch_bounds__(256, 4) void gsf_kernel(
        const float* __restrict__ x, float* __restrict__ out,
        const float* __restrict__ w1, const float* __restrict__ b1,
        const float* __restrict__ w2, const float* __restrict__ b2) {
    int t = threadIdx.x;
    int sub = t >> 6, c4 = t & 63;
    int b = blockIdx.x / 14, hq = blockIdx.x % 14;
    int h = hq*4 + sub;
    int bh = b*HH + h;

    __shared__ unsigned int s_f0;
    __shared__ int s_last;
    if (t == 0) s_f0 = atomicAdd(&g_flag[b], 0u);   // snapshot BEFORE ticketing

    size_t base = (size_t)bh*(WW*CC) + c4*4;
    const float* a2p = g_a2t + (size_t)b*WW*CC + c4*4;
    const float* a3p = g_a3 + bh*WW;
    float4 ra1 = *((const float4*)(g_a1 + (size_t)bh*CC) + c4);

    // ---- gap phase ----
    float4 acc = make_float4(0.f,0.f,0.f,0.f);
    #pragma unroll 8
    for (int w = 0; w < WW; ++w) {
        float4 xv = *(const float4*)(x + base + w*CC);
        float4 a2 = *(const float4*)(a2p + w*CC);
        float a3 = a3p[w];
        acc.x = fmaf(xv.x, ra1.x + a2.x + a3, acc.x);
        acc.y = fmaf(xv.y, ra1.y + a2.y + a3, acc.y);
        acc.z = fmaf(xv.z, ra1.z + a2.z + a3, acc.z);
        acc.w = fmaf(xv.w, ra1.w + a2.w + a3, acc.w);
    }
    __shared__ float4 sa[4][64];
    sa[sub][c4] = acc;
    __syncthreads();
    if (t < 64) {
        float4 s = sa[0][t];
        #pragma unroll
        for (int g = 1; g < 4; ++g) {
            float4 q = sa[g][t];
            s.x += q.x; s.y += q.y; s.z += q.z; s.w += q.w;
        }
        float* gp = g_gap + b*CC + t*4;
        atomicAdd(gp+0, s.x);
        atomicAdd(gp+1, s.y);
        atomicAdd(gp+2, s.z);
        atomicAdd(gp+3, s.w);
    }
    __threadfence();                                 // release our partial sums
    if (t == 0) {
        unsigned int old = atomicAdd(&g_ticket[b], 1u);
        s_last = ((old % 14u) == 13u);
    }
    __syncthreads();

    if (s_last) {
        __threadfence();                             // acquire
        __shared__ float g[CC];
        __shared__ float hbuf[32];
        g[t] = g_gap[b*CC + t] * (1.f/(HH*WW));
        __syncthreads();
        int d = t >> 3, grp = t & 7;
        float a = 0.f;
        #pragma unroll
        for (int k = 0; k < 32; ++k) {
            int c = grp + 8*k;
            a = fmaf(g[c], __ldg(w1 + c*32 + d), a);
        }
        a += __shfl_xor_sync(0xFFFFFFFFu, a, 1);
        a += __shfl_xor_sync(0xFFFFFFFFu, a, 2);
        a += __shfl_xor_sync(0xFFFFFFFFu, a, 4);
        if (grp == 0) hbuf[d] = fmaxf(a + __ldg(b1 + d), 0.f);
        __syncthreads();
        float av = __ldg(b2 + t);
        #pragma unroll
        for (int dd = 0; dd < 32; ++dd)
            av = fmaf(hbuf[dd], __ldg(w2 + dd*CC + t), av);
        g_cw[b*CC + t] = 1.f / (1.f + __expf(-av));
        __threadfence();                             // release cw
        __syncthreads();
        if (t == 0) atomicAdd(&g_flag[b], 1u);
    } else {
        if (t == 0) {
            while (atomicAdd(&g_flag[b], 0u) == s_f0) __nanosleep(200);
        }
        __syncthreads();
        __threadfence();                             // acquire cw
    }

    // ---- final phase: out = x * (a1+a2+a3) * cw (streaming stores) ----
    float4 rcw = *((const float4*)(g_cw + (size_t)b*CC) + c4);
    #pragma unroll 8
    for (int w = 0; w < WW; ++w) {
        float4 xv = *(const float4*)(x + base + w*CC);
        float4 a2 = *(const float4*)(a2p + w*CC);
        float a3 = a3p[w];
        float4 o;
        o.x = xv.x * (ra1.x + a2.x + a3) * rcw.x;
        o.y = xv.y * (ra1.y + a2.y + a3) * rcw.y;
        o.z = xv.z * (ra1.z + a2.z + a3) * rcw.z;
        o.w = xv.w * (ra1.w + a2.w + a3) * rcw.w;
        __stcs((float4*)(out + base + w*CC), o);
    }
}

// ---------------- launch ----------------------------------------------------------
extern "C" void kernel_launch(void* const* d_in, const int* in_sizes, int n_in,
                              void* d_out, int out_size) {
    const float* x   = (const float*)d_in[0];
    const float* c1w = (const float*)d_in[1];
    const float* c1b = (const float*)d_in[2];
    const float* b1g = (const float*)d_in[3];
    const float* b1b = (const float*)d_in[4];
    const float* b1m = (const float*)d_in[5];
    const float* b1v = (const float*)d_in[6];
    const float* c2w = (const float*)d_in[7];
    const float* c2b = (const float*)d_in[8];
    const float* b2g = (const float*)d_in[9];
    const float* b2b = (const float*)d_in[10];
    const float* b2m = (const float*)d_in[11];
    const float* b2v = (const float*)d_in[12];
    const float* c3w = (const float*)d_in[13];
    const float* c3b = (const float*)d_in[14];
    const float* b3g = (const float*)d_in[15];
    const float* b3b = (const float*)d_in[16];
    const float* b3m = (const float*)d_in[17];
    const float* b3v = (const float*)d_in[18];
    const float* sw1 = (const float*)d_in[19];
    const float* sb1 = (const float*)d_in[20];
    const float* sw2 = (const float*)d_in[21];
    const float* sb2 = (const float*)d_in[22];
    float* out = (float*)d_out;

    pools_kernel<<<2*NB, 256>>>(x);
    conv_all_kernel<<<1472, 256>>>(
        c1w, c1b, b1g, b1b, b1m, b1v,
        c2w, c2b, b2g, b2b, b2m, b2v,
        c3w, c3b, b3g, b3b, b3m, b3v);
    gsf_kernel<<<NB, 256>>>(x, out, sw1, sb1, sw2, sb2);
}

// round 17
// speedup vs baseline: 1.6576x; 1.1192x over previous
#include <cuda_runtime.h>
#include <math.h>
#include <float.h>

#define BB 32
#define HH 56
#define WW 56
#define CC 256
#define HW (HH*WW)
#define NB (BB*14)   // 448 blocks per streaming pass (4 rows x 64 c-quads each)

// ---------------- scratch (device globals) ---------------------------------------
__device__ __align__(16) float g_pool1[BB*HH*CC*2];   // [b][h][c][{max,mean}]
__device__ __align__(16) float g_pool2[BB*CC*WW*2];   // [b][c][w][{max,mean}]
__device__ __align__(16) float g_pool3[BB*HH*WW*2];   // [b][h][w][{max,mean}]
__device__ __align__(16) float g_a1 [BB*HH*CC];       // [b][h][c]
__device__ __align__(16) float g_a2t[BB*WW*CC];       // [b][w][c]
__device__ __align__(16) float g_a3 [BB*HH*WW];       // [b][h][w]
__device__ __align__(16) float g_gap[BB*CC];          // atomically-reduced gap sums
__device__ __align__(16) float g_cw[BB*CC];           // SE channel gate
__device__ unsigned int g_ticket[BB];                 // monotonic arrival tickets
__device__ unsigned int g_flag[BB];                   // monotonic per-batch done flag

__device__ __forceinline__ float4 f4max(float4 a, float4 b) {
    return make_float4(fmaxf(a.x,b.x), fmaxf(a.y,b.y), fmaxf(a.z,b.z), fmaxf(a.w,b.w));
}

// ---------------- all three pools, one kernel (also zeroes g_gap) -----------------
// Batch-grouped blocks (pool13/pool2 of one batch co-resident -> L2 reuse).
// MLP=4 batching at 3 blocks/SM (96 outstanding loads per SM).
__global__ __launch_bounds__(256, 3) void pools_kernel(const float* __restrict__ x) {
    int t = threadIdx.x;
    int sub = t >> 6;          // 0..3
    int c4  = t & 63;          // c-quad index

    if (blockIdx.x < 32) g_gap[blockIdx.x*CC + t] = 0.f;   // zero for gsf atomics

    int b = blockIdx.x / 28;
    int j = blockIdx.x % 28;

    if (j < 14) {
        int hq = j;
        int h = hq*4 + sub;
        int bh = b*HH + h;
        const float* xp = x + (size_t)bh*(WW*CC) + c4*4;

        int lane = t & 31;
        int half = c4 >> 5;
        __shared__ float2 s3[4][WW][2];

        float4 mx = make_float4(-FLT_MAX,-FLT_MAX,-FLT_MAX,-FLT_MAX);
        float4 sm = make_float4(0.f,0.f,0.f,0.f);

        #pragma unroll
        for (int w0 = 0; w0 < WW; w0 += 4) {
            float4 v0 = *(const float4*)(xp + (w0+0)*CC);
            float4 v1 = *(const float4*)(xp + (w0+1)*CC);
            float4 v2 = *(const float4*)(xp + (w0+2)*CC);
            float4 v3 = *(const float4*)(xp + (w0+3)*CC);
            mx = f4max(mx, v0); mx = f4max(mx, v1);
            mx = f4max(mx, v2); mx = f4max(mx, v3);
            sm.x += v0.x+v1.x+v2.x+v3.x;
            sm.y += v0.y+v1.y+v2.y+v3.y;
            sm.z += v0.z+v1.z+v2.z+v3.z;
            sm.w += v0.w+v1.w+v2.w+v3.w;
            float m0 = fmaxf(fmaxf(v0.x,v0.y), fmaxf(v0.z,v0.w));
            float m1 = fmaxf(fmaxf(v1.x,v1.y), fmaxf(v1.z,v1.w));
            float m2 = fmaxf(fmaxf(v2.x,v2.y), fmaxf(v2.z,v2.w));
            float m3 = fmaxf(fmaxf(v3.x,v3.y), fmaxf(v3.z,v3.w));
            float s0 = v0.x+v0.y+v0.z+v0.w;
            float s1 = v1.x+v1.y+v1.z+v1.w;
            float s2 = v2.x+v2.y+v2.z+v2.w;
            float s3v = v3.x+v3.y+v3.z+v3.w;
            #pragma unroll
            for (int off = 16; off; off >>= 1) {
                m0 = fmaxf(m0, __shfl_xor_sync(0xFFFFFFFFu, m0, off));
                m1 = fmaxf(m1, __shfl_xor_sync(0xFFFFFFFFu, m1, off));
                m2 = fmaxf(m2, __shfl_xor_sync(0xFFFFFFFFu, m2, off));
                m3 = fmaxf(m3, __shfl_xor_sync(0xFFFFFFFFu, m3, off));
                s0 += __shfl_xor_sync(0xFFFFFFFFu, s0, off);
                s1 += __shfl_xor_sync(0xFFFFFFFFu, s1, off);
                s2 += __shfl_xor_sync(0xFFFFFFFFu, s2, off);
                s3v += __shfl_xor_sync(0xFFFFFFFFu, s3v, off);
            }
            if (lane == 0) {
                s3[sub][w0+0][half] = make_float2(m0, s0);
                s3[sub][w0+1][half] = make_float2(m1, s1);
                s3[sub][w0+2][half] = make_float2(m2, s2);
                s3[sub][w0+3][half] = make_float2(m3, s3v);
            }
        }
        {
            const float invw = 1.f/WW;
            float4* o = (float4*)(g_pool1 + ((size_t)bh*CC + c4*4)*2);
            o[0] = make_float4(mx.x, sm.x*invw, mx.y, sm.y*invw);
            o[1] = make_float4(mx.z, sm.z*invw, mx.w, sm.w*invw);
        }
        __syncthreads();
        if (t < 224) {
            int hl = t / WW, w = t % WW;
            float2 p0 = s3[hl][w][0], p1 = s3[hl][w][1];
            int o = ((b*HH + hq*4 + hl)*WW + w)*2;
            g_pool3[o]   = fmaxf(p0.x, p1.x);
            g_pool3[o+1] = (p0.y + p1.y) * (1.f/CC);
        }
    } else {
        int wq = j - 14;
        int w = wq*4 + sub;
        const float* xp = x + ((size_t)b*HW + w)*CC + c4*4;
        float4 mx = make_float4(-FLT_MAX,-FLT_MAX,-FLT_MAX,-FLT_MAX);
        float4 sm = make_float4(0.f,0.f,0.f,0.f);
        #pragma unroll
        for (int h0 = 0; h0 < HH; h0 += 4) {
            float4 v0 = *(const float4*)(xp + (size_t)(h0+0)*WW*CC);
            float4 v1 = *(const float4*)(xp + (size_t)(h0+1)*WW*CC);
            float4 v2 = *(const float4*)(xp + (size_t)(h0+2)*WW*CC);
            float4 v3 = *(const float4*)(xp + (size_t)(h0+3)*WW*CC);
            mx = f4max(mx, v0); mx = f4max(mx, v1);
            mx = f4max(mx, v2); mx = f4max(mx, v3);
            sm.x += v0.x+v1.x+v2.x+v3.x;
            sm.y += v0.y+v1.y+v2.y+v3.y;
            sm.z += v0.z+v1.z+v2.z+v3.z;
            sm.w += v0.w+v1.w+v2.w+v3.w;
        }
        const float invh = 1.f/HH;
        float2* o = (float2*)g_pool2 + ((size_t)b*CC + c4*4)*WW + w;
        o[0]    = make_float2(mx.x, sm.x*invh);
        o[WW]   = make_float2(mx.y, sm.y*invh);
        o[2*WW] = make_float2(mx.z, sm.z*invh);
        o[3*WW] = make_float2(mx.w, sm.w*invh);
    }
}

// ---------------- 7x7 conv (2ch->1) + BN + sigmoid, smem-tiled, branchless -------
template<int HC, int WC, int MODE>
__device__ __forceinline__ void do_conv(
    float2* tile, float2* wsm,
    const float* __restrict__ in, float* __restrict__ out,
    int b, int t0, float sc, float sh, float bs)
{
    const int TI = 8;
    const int PW = WC + 6;
    int tid = threadIdx.x;
    int i0 = t0 * TI;

    const float2* inb = (const float2*)in + (size_t)b*HC*WC;
    for (int idx = tid; idx < (TI+6)*PW; idx += 256) {
        int r = idx / PW, col = idx - r*PW;
        int i2 = i0 + r - 3, j2 = col - 3;
        float2 v = make_float2(0.f, 0.f);
        if (i2 >= 0 && i2 < HC && j2 >= 0 && j2 < WC)
            v = inb[i2*WC + j2];
        tile[idx] = v;
    }
    __syncthreads();

    for (int o = tid; o < TI*WC; o += 256) {
        int r = o / WC, j = o - r*WC;
        const float2* base = tile + r*PW + j;
        float acc = bs;
        #pragma unroll
        for (int kh = 0; kh < 7; ++kh) {
            #pragma unroll
            for (int kw = 0; kw < 7; ++kw) {
                float2 v = base[kh*PW + kw];
                float2 w = wsm[kh*7 + kw];
                acc = fmaf(v.x, w.x, acc);
                acc = fmaf(v.y, w.y, acc);
            }
        }
        float y = acc*sc + sh;
        float a = 1.f / (1.f + __expf(-y));
        int i = i0 + r;
        size_t oo = MODE ? ((size_t)b*WC + j)*HC + i
                         : ((size_t)b*HC + i)*WC + j;
        out[oo] = a;
    }
}

__global__ void conv_all_kernel(
    const float* __restrict__ c1w, const float* __restrict__ c1b,
    const float* __restrict__ b1g, const float* __restrict__ b1b,
    const float* __restrict__ b1m, const float* __restrict__ b1v,
    const float* __restrict__ c2w, const float* __restrict__ c2b,
    const float* __restrict__ b2g, const float* __restrict__ b2b,
    const float* __restrict__ b2m, const float* __restrict__ b2v,
    const float* __restrict__ c3w, const float* __restrict__ c3b,
    const float* __restrict__ b3g, const float* __restrict__ b3b,
    const float* __restrict__ b3m, const float* __restrict__ b3v)
{
    __shared__ float2 tile[14*262];
    __shared__ float2 wsm[49];

    int bx = blockIdx.x;
    int which, b, t0;
    const float *wc, *bc, *bg, *bb, *bm, *bv;
    if (bx < 224)        { which = 0; int r = bx;        b = r/7;  t0 = r%7;
                           wc=c1w; bc=c1b; bg=b1g; bb=b1b; bm=b1m; bv=b1v; }
    else if (bx < 1248)  { which = 1; int r = bx - 224;  b = r/32; t0 = r%32;
                           wc=c2w; bc=c2b; bg=b2g; bb=b2b; bm=b2m; bv=b2v; }
    else                 { which = 2; int r = bx - 1248; b = r/7;  t0 = r%7;
                           wc=c3w; bc=c3b; bg=b3g; bb=b3b; bm=b3m; bv=b3v; }

    if (threadIdx.x < 49) wsm[threadIdx.x] = ((const float2*)wc)[threadIdx.x];
    float sc = bg[0] * rsqrtf(bv[0] + 1e-3f);
    float sh = bb[0] - bm[0]*sc;
    float bs = bc[0];
    __syncthreads();

    if (which == 0)
        do_conv<HH, CC, 0>(tile, wsm, g_pool1, g_a1,  b, t0, sc, sh, bs);
    else if (which == 1)
        do_conv<CC, WW, 1>(tile, wsm, g_pool2, g_a2t, b, t0, sc, sh, bs);
    else
        do_conv<HH, WW, 0>(tile, wsm, g_pool3, g_a3,  b, t0, sc, sh, bs);
}

// ---------------- fused gap + SE + final ------------------------------------------
// gap/final loops explicitly 4-batched so ptxas front-batches loads within
// the 64-reg budget of occupancy 4.
__global__ __launch_bounds__(256, 4) void gsf_kernel(
        const float* __restrict__ x, float* __restrict__ out,
        const float* __restrict__ w1, const float* __restrict__ b1,
        const float* __restrict__ w2, const float* __restrict__ b2) {
    int t = threadIdx.x;
    int sub = t >> 6, c4 = t & 63;
    int b = blockIdx.x / 14, hq = blockIdx.x % 14;
    int h = hq*4 + sub;
    int bh = b*HH + h;

    __shared__ unsigned int s_f0;
    __shared__ int s_last;
    if (t == 0) s_f0 = atomicAdd(&g_flag[b], 0u);   // snapshot BEFORE ticketing

    size_t base = (size_t)bh*(WW*CC) + c4*4;
    const float* a2p = g_a2t + (size_t)b*WW*CC + c4*4;
    const float* a3p = g_a3 + bh*WW;
    float4 ra1 = *((const float4*)(g_a1 + (size_t)bh*CC) + c4);

    // ---- gap phase: 4-batched loads ----
    float4 acc = make_float4(0.f,0.f,0.f,0.f);
    #pragma unroll
    for (int w0 = 0; w0 < WW; w0 += 4) {
        float4 x0 = *(const float4*)(x + base + (w0+0)*CC);
        float4 x1 = *(const float4*)(x + base + (w0+1)*CC);
        float4 x2 = *(const float4*)(x + base + (w0+2)*CC);
        float4 x3 = *(const float4*)(x + base + (w0+3)*CC);
        float4 a20 = *(const float4*)(a2p + (w0+0)*CC);
        float4 a21 = *(const float4*)(a2p + (w0+1)*CC);
        float4 a22 = *(const float4*)(a2p + (w0+2)*CC);
        float4 a23 = *(const float4*)(a2p + (w0+3)*CC);
        float a30 = a3p[w0+0], a31 = a3p[w0+1], a32 = a3p[w0+2], a33 = a3p[w0+3];
        acc.x = fmaf(x0.x, ra1.x + a20.x + a30, acc.x);
        acc.y = fmaf(x0.y, ra1.y + a20.y + a30, acc.y);
        acc.z = fmaf(x0.z, ra1.z + a20.z + a30, acc.z);
        acc.w = fmaf(x0.w, ra1.w + a20.w + a30, acc.w);
        acc.x = fmaf(x1.x, ra1.x + a21.x + a31, acc.x);
        acc.y = fmaf(x1.y, ra1.y + a21.y + a31, acc.y);
        acc.z = fmaf(x1.z, ra1.z + a21.z + a31, acc.z);
        acc.w = fmaf(x1.w, ra1.w + a21.w + a31, acc.w);
        acc.x = fmaf(x2.x, ra1.x + a22.x + a32, acc.x);
        acc.y = fmaf(x2.y, ra1.y + a22.y + a32, acc.y);
        acc.z = fmaf(x2.z, ra1.z + a22.z + a32, acc.z);
        acc.w = fmaf(x2.w, ra1.w + a22.w + a32, acc.w);
        acc.x = fmaf(x3.x, ra1.x + a23.x + a33, acc.x);
        acc.y = fmaf(x3.y, ra1.y + a23.y + a33, acc.y);
        acc.z = fmaf(x3.z, ra1.z + a23.z + a33, acc.z);
        acc.w = fmaf(x3.w, ra1.w + a23.w + a33, acc.w);
    }
    __shared__ float4 sa[4][64];
    sa[sub][c4] = acc;
    __syncthreads();
    if (t < 64) {
        float4 s = sa[0][t];
        #pragma unroll
        for (int g = 1; g < 4; ++g) {
            float4 q = sa[g][t];
            s.x += q.x; s.y += q.y; s.z += q.z; s.w += q.w;
        }
        float* gp = g_gap + b*CC + t*4;
        atomicAdd(gp+0, s.x);
        atomicAdd(gp+1, s.y);
        atomicAdd(gp+2, s.z);
        atomicAdd(gp+3, s.w);
    }
    __threadfence();                                 // release our partial sums
    if (t == 0) {
        unsigned int old = atomicAdd(&g_ticket[b], 1u);
        s_last = ((old % 14u) == 13u);
    }
    __syncthreads();

    if (s_last) {
        __threadfence();                             // acquire
        __shared__ float g[CC];
        __shared__ float hbuf[32];
        g[t] = g_gap[b*CC + t] * (1.f/(HH*WW));
        __syncthreads();
        int d = t >> 3, grp = t & 7;
        float a = 0.f;
        #pragma unroll
        for (int k = 0; k < 32; ++k) {
            int c = grp + 8*k;
            a = fmaf(g[c], __ldg(w1 + c*32 + d), a);
        }
        a += __shfl_xor_sync(0xFFFFFFFFu, a, 1);
        a += __shfl_xor_sync(0xFFFFFFFFu, a, 2);
        a += __shfl_xor_sync(0xFFFFFFFFu, a, 4);
        if (grp == 0) hbuf[d] = fmaxf(a + __ldg(b1 + d), 0.f);
        __syncthreads();
        float av = __ldg(b2 + t);
        #pragma unroll
        for (int dd = 0; dd < 32; ++dd)
            av = fmaf(hbuf[dd], __ldg(w2 + dd*CC + t), av);
        g_cw[b*CC + t] = 1.f / (1.f + __expf(-av));
        __threadfence();                             // release cw
        __syncthreads();
        if (t == 0) atomicAdd(&g_flag[b], 1u);
    } else {
        if (t == 0) {
            while (atomicAdd(&g_flag[b], 0u) == s_f0) __nanosleep(200);
        }
        __syncthreads();
        __threadfence();                             // acquire cw
    }

    // ---- final phase: 4-batched, streaming stores ----
    float4 rcw = *((const float4*)(g_cw + (size_t)b*CC) + c4);
    #pragma unroll
    for (int w0 = 0; w0 < WW; w0 += 4) {
        float4 x0 = *(const float4*)(x + base + (w0+0)*CC);
        float4 x1 = *(const float4*)(x + base + (w0+1)*CC);
        float4 x2 = *(const float4*)(x + base + (w0+2)*CC);
        float4 x3 = *(const float4*)(x + base + (w0+3)*CC);
        float4 a20 = *(const float4*)(a2p + (w0+0)*CC);
        float4 a21 = *(const float4*)(a2p + (w0+1)*CC);
        float4 a22 = *(const float4*)(a2p + (w0+2)*CC);
        float4 a23 = *(const float4*)(a2p + (w0+3)*CC);
        float a30 = a3p[w0+0], a31 = a3p[w0+1], a32 = a3p[w0+2], a33 = a3p[w0+3];
        float4 o0, o1, o2, o3;
        o0.x = x0.x * (ra1.x + a20.x + a30) * rcw.x;
        o0.y = x0.y * (ra1.y + a20.y + a30) * rcw.y;
        o0.z = x0.z * (ra1.z + a20.z + a30) * rcw.z;
        o0.w = x0.w * (ra1.w + a20.w + a30) * rcw.w;
        o1.x = x1.x * (ra1.x + a21.x + a31) * rcw.x;
        o1.y = x1.y * (ra1.y + a21.y + a31) * rcw.y;
        o1.z = x1.z * (ra1.z + a21.z + a31) * rcw.z;
        o1.w = x1.w * (ra1.w + a21.w + a31) * rcw.w;
        o2.x = x2.x * (ra1.x + a22.x + a32) * rcw.x;
        o2.y = x2.y * (ra1.y + a22.y + a32) * rcw.y;
        o2.z = x2.z * (ra1.z + a22.z + a32) * rcw.z;
        o2.w = x2.w * (ra1.w + a22.w + a32) * rcw.w;
        o3.x = x3.x * (ra1.x + a23.x + a33) * rcw.x;
        o3.y = x3.y * (ra1.y + a23.y + a33) * rcw.y;
        o3.z = x3.z * (ra1.z + a23.z + a33) * rcw.z;
        o3.w = x3.w * (ra1.w + a23.w + a33) * rcw.w;
        __stcs((float4*)(out + base + (w0+0)*CC), o0);
        __stcs((float4*)(out + base + (w0+1)*CC), o1);
        __stcs((float4*)(out + base + (w0+2)*CC), o2);
        __stcs((float4*)(out + base + (w0+3)*CC), o3);
    }
}

// ---------------- launch ----------------------------------------------------------
extern "C" void kernel_launch(void* const* d_in, const int* in_sizes, int n_in,
                              void* d_out, int out_size) {
    const float* x   = (const float*)d_in[0];
    const float* c1w = (const float*)d_in[1];
    const float* c1b = (const float*)d_in[2];
    const float* b1g = (const float*)d_in[3];
    const float* b1b = (const float*)d_in[4];
    const float* b1m = (const float*)d_in[5];
    const float* b1v = (const float*)d_in[6];
    const float* c2w = (const float*)d_in[7];
    const float* c2b = (const float*)d_in[8];
    const float* b2g = (const float*)d_in[9];
    const float* b2b = (const float*)d_in[10];
    const float* b2m = (const float*)d_in[11];
    const float* b2v = (const float*)d_in[12];
    const float* c3w = (const float*)d_in[13];
    const float* c3b = (const float*)d_in[14];
    const float* b3g = (const float*)d_in[15];
    const float* b3b = (const float*)d_in[16];
    const float* b3m = (const float*)d_in[17];
    const float* b3v = (const float*)d_in[18];
    const float* sw1 = (const float*)d_in[19];
    const float* sb1 = (const float*)d_in[20];
    const float* sw2 = (const float*)d_in[21];
    const float* sb2 = (const float*)d_in[22];
    float* out = (float*)d_out;

    pools_kernel<<<2*NB, 256>>>(x);
    conv_all_kernel<<<1472, 256>>>(
        c1w, c1b, b1g, b1b, b1m, b1v,
        c2w, c2b, b2g, b2b, b2m, b2v,
        c3w, c3b, b3g, b3b, b3m, b3v);
    gsf_kernel<<<NB, 256>>>(x, out, sw1, sb1, sw2, sb2);
}